// round 1
// baseline (speedup 1.0000x reference)
#include <cuda_runtime.h>
#include <math.h>

#define NN 50000      // nodes
#define NE 800000     // edges
#define NG 128        // graphs
#define FX 92         // node feature dim
#define FE 41         // edge feature dim
#define HD 64         // hidden
#define NCV 3         // conv layers
#define BN_EPS 1e-5f

// ---------------- device scratch (static: no runtime allocation) ----------------
__device__ float g_h[NN * HD];                        // current node features
__device__ float g_acc[NN * HD];                      // residual + message accumulator
__device__ float g_HN[NN * 4 * HD];                   // [N,256]: h@[Wf_i|Wf_j|Ws_i|Ws_j]
__device__ float g_EW[(long long)NE * 2 * HD];        // [E,128]: per-layer edge preactivation (f|s)
__device__ float g_Wce[NCV * FE * 2 * HD];            // folded edge weights [3][41][128]
__device__ float g_bce[NCV * 2 * HD];                 // folded edge bias   [3][128]
__device__ float g_Wnode[NCV * HD * 4 * HD];          // node weights [3][64][256]
__device__ float g_sum[HD];
__device__ float g_sumsq[HD];
__device__ float g_gsum[NG * HD];
__device__ float g_gcnt[NG];

__device__ __forceinline__ float sigmoid_f(float x) {
    return 1.0f / (1.0f + __expf(-x));
}
__device__ __forceinline__ float softplus_f(float x) {
    return fmaxf(x, 0.0f) + log1pf(__expf(-fabsf(x)));
}

// ---------------- prep: fold weights ----------------
// Wce[a][k][j]   = sum_m W_emb2[k][m] * W{f,s}[a][128+m][j]      (e-block folded thru emb2)
// bce[a][j]      = b{f,s}[a][j] + sum_m b_emb2[m] * W{f,s}[a][128+m][j]
// Wnode[a][m][j] = [Wf rows 0:64 | Wf rows 64:128 | Ws rows 0:64 | Ws rows 64:128]
__global__ void prep_kernel(const float* __restrict__ W_emb2, const float* __restrict__ b_emb2,
                            const float* __restrict__ Wf, const float* __restrict__ bf,
                            const float* __restrict__ Ws, const float* __restrict__ bs) {
    int idx = blockIdx.x * blockDim.x + threadIdx.x;
    const int N_WCE = NCV * FE * 2 * HD;  // 15744
    const int N_BCE = NCV * 2 * HD;       // 384
    const int N_WND = NCV * HD * 4 * HD;  // 49152
    if (idx < N_WCE) {
        int j = idx % (2 * HD);
        int k = (idx / (2 * HD)) % FE;
        int a = idx / (2 * HD * FE);
        const float* Wb = (j < HD) ? Wf : Ws;
        int jj = j & (HD - 1);
        float s = 0.f;
        #pragma unroll 8
        for (int m = 0; m < HD; m++)
            s = fmaf(W_emb2[k * HD + m], Wb[(a * 3 * HD + 2 * HD + m) * HD + jj], s);
        g_Wce[idx] = s;
    } else if (idx < N_WCE + N_BCE) {
        int t = idx - N_WCE;
        int j = t % (2 * HD);
        int a = t / (2 * HD);
        const float* Wb = (j < HD) ? Wf : Ws;
        const float* bb = (j < HD) ? bf : bs;
        int jj = j & (HD - 1);
        float s = bb[a * HD + jj];
        #pragma unroll 8
        for (int m = 0; m < HD; m++)
            s = fmaf(b_emb2[m], Wb[(a * 3 * HD + 2 * HD + m) * HD + jj], s);
        g_bce[t] = s;
    } else if (idx < N_WCE + N_BCE + N_WND) {
        int t = idx - N_WCE - N_BCE;
        int j = t % (4 * HD);
        int m = (t / (4 * HD)) % HD;
        int a = t / (4 * HD * HD);
        int blk = j / HD;
        int jj = j & (HD - 1);
        const float* Wsel = (blk < 2) ? Wf : Ws;
        int roff = (blk & 1) ? HD : 0;
        g_Wnode[t] = Wsel[(a * 3 * HD + roff + m) * HD + jj];
    }
}

// ---------------- generic fp32 GEMM: C[M,NC] = A[M,K] @ B[K,NC] (+ bias) ----------------
// B fully resident in smem; register tile RPT rows x 8 cols per thread.
template <int K, int NC, int CT, int RT, int RPT>
__global__ void gemm_bias_kernel(const float* __restrict__ A, const float* __restrict__ B,
                                 const float* __restrict__ bias, float* __restrict__ C, int M) {
    constexpr int TR = RT * RPT;
    constexpr int KP = K + 1;
    constexpr int NT = CT * RT;
    extern __shared__ float smem[];
    float* Bs = smem;             // K*NC
    float* As = smem + K * NC;    // TR*KP
    int tid = threadIdx.x;
    int tx = tid % CT;
    int ty = tid / CT;
    for (int i = tid; i < K * NC; i += NT) Bs[i] = B[i];
    float bv[8];
    #pragma unroll
    for (int c = 0; c < 8; c++) bv[c] = bias ? bias[tx * 8 + c] : 0.f;

    for (int tile = blockIdx.x; (long long)tile * TR < M; tile += gridDim.x) {
        int row0 = tile * TR;
        __syncthreads();
        for (int i = tid; i < TR * K; i += NT) {
            int r = i / K;
            int k = i - r * K;
            int gr = row0 + r;
            As[r * KP + k] = (gr < M) ? A[(long long)gr * K + k] : 0.f;
        }
        __syncthreads();
        float acc[RPT][8];
        #pragma unroll
        for (int r = 0; r < RPT; r++)
            #pragma unroll
            for (int c = 0; c < 8; c++) acc[r][c] = 0.f;
        #pragma unroll 4
        for (int k = 0; k < K; k++) {
            float4 b0 = *reinterpret_cast<const float4*>(&Bs[k * NC + tx * 8]);
            float4 b1 = *reinterpret_cast<const float4*>(&Bs[k * NC + tx * 8 + 4]);
            #pragma unroll
            for (int r = 0; r < RPT; r++) {
                float a = As[(ty * RPT + r) * KP + k];
                acc[r][0] = fmaf(a, b0.x, acc[r][0]);
                acc[r][1] = fmaf(a, b0.y, acc[r][1]);
                acc[r][2] = fmaf(a, b0.z, acc[r][2]);
                acc[r][3] = fmaf(a, b0.w, acc[r][3]);
                acc[r][4] = fmaf(a, b1.x, acc[r][4]);
                acc[r][5] = fmaf(a, b1.y, acc[r][5]);
                acc[r][6] = fmaf(a, b1.z, acc[r][6]);
                acc[r][7] = fmaf(a, b1.w, acc[r][7]);
            }
        }
        #pragma unroll
        for (int r = 0; r < RPT; r++) {
            int gr = row0 + ty * RPT + r;
            if (gr < M) {
                float4 o0 = make_float4(acc[r][0] + bv[0], acc[r][1] + bv[1],
                                        acc[r][2] + bv[2], acc[r][3] + bv[3]);
                float4 o1 = make_float4(acc[r][4] + bv[4], acc[r][5] + bv[5],
                                        acc[r][6] + bv[6], acc[r][7] + bv[7]);
                float* cp = &C[(long long)gr * NC + tx * 8];
                *reinterpret_cast<float4*>(cp) = o0;
                *reinterpret_cast<float4*>(cp + 4) = o1;
            }
        }
    }
}

// ---------------- residual copy + stat/pool zeroing ----------------
__global__ void copyzero_kernel(int zero_pool) {
    int idx = blockIdx.x * blockDim.x + threadIdx.x;
    if (idx < NN * HD) g_acc[idx] = g_h[idx];
    if (idx < HD) { g_sum[idx] = 0.f; g_sumsq[idx] = 0.f; }
    if (zero_pool) {
        if (idx < NG * HD) g_gsum[idx] = 0.f;
        if (idx < NG) g_gcnt[idx] = 0.f;
    }
}

// ---------------- edge message + scatter ----------------
// 16 threads per edge, float4 per thread.
// HN row = [f_i(0:64) | f_j(64:128) | s_i(128:192) | s_j(192:256)]
// EW row = [f(0:64) | s(64:128)] (includes all biases)
__global__ void edge_kernel(const int* __restrict__ ei) {
    int t = blockIdx.x * blockDim.x + threadIdx.x;
    int e = t >> 4;
    int lane = t & 15;
    if (e >= NE) return;
    int s = ei[e];           // source (x_j)
    int d = ei[NE + e];      // target (x_i / aggregation index)
    const float4* HN4 = reinterpret_cast<const float4*>(g_HN);
    const float4* EW4 = reinterpret_cast<const float4*>(g_EW);
    float4 fi = HN4[(long long)d * 64 + lane];
    float4 fj = HN4[(long long)s * 64 + 16 + lane];
    float4 si = HN4[(long long)d * 64 + 32 + lane];
    float4 sj = HN4[(long long)s * 64 + 48 + lane];
    float4 ef = EW4[(long long)e * 32 + lane];
    float4 es = EW4[(long long)e * 32 + 16 + lane];
    float m0 = sigmoid_f(fi.x + fj.x + ef.x) * softplus_f(si.x + sj.x + es.x);
    float m1 = sigmoid_f(fi.y + fj.y + ef.y) * softplus_f(si.y + sj.y + es.y);
    float m2 = sigmoid_f(fi.z + fj.z + ef.z) * softplus_f(si.z + sj.z + es.z);
    float m3 = sigmoid_f(fi.w + fj.w + ef.w) * softplus_f(si.w + sj.w + es.w);
    float* ap = &g_acc[(long long)d * HD + lane * 4];
    atomicAdd(ap + 0, m0);
    atomicAdd(ap + 1, m1);
    atomicAdd(ap + 2, m2);
    atomicAdd(ap + 3, m3);
}

// ---------------- BN stats: per-column sum & sumsq ----------------
__global__ void stats_kernel() {
    __shared__ float s_s[HD], s_q[HD];
    int tid = threadIdx.x;
    if (tid < HD) { s_s[tid] = 0.f; s_q[tid] = 0.f; }
    __syncthreads();
    int col = tid & (HD - 1);  // stride is multiple of 64 -> col fixed per thread
    float ls = 0.f, lq = 0.f;
    for (int idx = blockIdx.x * blockDim.x + tid; idx < NN * HD; idx += gridDim.x * blockDim.x) {
        float v = g_acc[idx];
        ls += v;
        lq = fmaf(v, v, lq);
    }
    atomicAdd(&s_s[col], ls);
    atomicAdd(&s_q[col], lq);
    __syncthreads();
    if (tid < HD) { atomicAdd(&g_sum[tid], s_s[tid]); atomicAdd(&g_sumsq[tid], s_q[tid]); }
}

// ---------------- BN normalize (+relu) (+fused pooling on last layer) ----------------
__global__ void bn_kernel(const float* __restrict__ gamma, const float* __restrict__ beta,
                          int do_relu, int do_pool, const int* __restrict__ batch) {
    int idx = blockIdx.x * blockDim.x + threadIdx.x;
    if (idx >= NN * HD) return;
    int col = idx & (HD - 1);
    const float invn = 1.0f / (float)NN;
    float mu = g_sum[col] * invn;
    float var = g_sumsq[col] * invn - mu * mu;
    var = fmaxf(var, 0.f);
    float v = (g_acc[idx] - mu) * rsqrtf(var + BN_EPS) * gamma[col] + beta[col];
    if (do_relu) v = fmaxf(v, 0.f);
    g_h[idx] = v;
    if (do_pool) {
        int node = idx >> 6;
        int b = batch[node];
        atomicAdd(&g_gsum[b * HD + col], v);
        if (col == 0) atomicAdd(&g_gcnt[b], 1.0f);
    }
}

// ---------------- final MLP: one block, one graph per thread ----------------
__global__ void mlp_kernel(const float* __restrict__ W1, const float* __restrict__ b1,
                           const float* __restrict__ W2, const float* __restrict__ b2,
                           const float* __restrict__ Wo, const float* __restrict__ bo,
                           float* __restrict__ out) {
    __shared__ float sW1[HD * HD], sW2[HD * HD], sWo[HD], sb1[HD], sb2[HD];
    int tid = threadIdx.x;
    for (int i = tid; i < HD * HD; i += blockDim.x) { sW1[i] = W1[i]; sW2[i] = W2[i]; }
    if (tid < HD) { sWo[tid] = Wo[tid]; sb1[tid] = b1[tid]; sb2[tid] = b2[tid]; }
    __syncthreads();
    if (tid < NG) {
        float inv = 1.0f / fmaxf(g_gcnt[tid], 1.0f);
        float v[HD], y[HD];
        #pragma unroll
        for (int k = 0; k < HD; k++) v[k] = g_gsum[tid * HD + k] * inv;
        #pragma unroll 1
        for (int j = 0; j < HD; j++) {
            float s = sb1[j];
            #pragma unroll
            for (int k = 0; k < HD; k++) s = fmaf(v[k], sW1[k * HD + j], s);
            y[j] = softplus_f(s);
        }
        float o = bo[0];
        #pragma unroll 1
        for (int j = 0; j < HD; j++) {
            float s = sb2[j];
            #pragma unroll
            for (int k = 0; k < HD; k++) s = fmaf(y[k], sW2[k * HD + j], s);
            o = fmaf(softplus_f(s), sWo[j], o);
        }
        out[tid] = o;
    }
}

// ---------------- host launcher ----------------
template <int K, int NC, int CT, int RT, int RPT>
static void launch_gemm(const float* A, const float* B, const float* bias, float* C, int M) {
    constexpr int TR = RT * RPT;
    constexpr int KP = K + 1;
    static_assert(CT * 8 == NC, "col threads x 8 must equal NC");
    size_t sm = (size_t)(K * NC + TR * KP) * sizeof(float);
    if (sm > 48 * 1024) {
        cudaFuncSetAttribute(gemm_bias_kernel<K, NC, CT, RT, RPT>,
                             cudaFuncAttributeMaxDynamicSharedMemorySize, (int)sm);
    }
    int tiles = (M + TR - 1) / TR;
    gemm_bias_kernel<K, NC, CT, RT, RPT><<<tiles, CT * RT, sm>>>(A, B, bias, C, M);
}

extern "C" void kernel_launch(void* const* d_in, const int* in_sizes, int n_in,
                              void* d_out, int out_size) {
    const float* x         = (const float*)d_in[0];
    const float* edge_attr = (const float*)d_in[1];
    const int*   ei        = (const int*)d_in[2];
    const int*   batch     = (const int*)d_in[3];
    const float* W_emb1    = (const float*)d_in[4];
    const float* b_emb1    = (const float*)d_in[5];
    const float* W_emb2    = (const float*)d_in[6];
    const float* b_emb2    = (const float*)d_in[7];
    const float* Wf        = (const float*)d_in[8];
    const float* bf        = (const float*)d_in[9];
    const float* Ws        = (const float*)d_in[10];
    const float* bs        = (const float*)d_in[11];
    const float* gamma     = (const float*)d_in[12];
    const float* beta      = (const float*)d_in[13];
    const float* W1        = (const float*)d_in[14];
    const float* b1        = (const float*)d_in[15];
    const float* W2        = (const float*)d_in[16];
    const float* b2        = (const float*)d_in[17];
    const float* Wo        = (const float*)d_in[18];
    const float* bo        = (const float*)d_in[19];
    float* out = (float*)d_out;

    float *p_h, *p_HN, *p_EW, *p_Wce, *p_bce, *p_Wnode;
    cudaGetSymbolAddress((void**)&p_h, g_h);
    cudaGetSymbolAddress((void**)&p_HN, g_HN);
    cudaGetSymbolAddress((void**)&p_EW, g_EW);
    cudaGetSymbolAddress((void**)&p_Wce, g_Wce);
    cudaGetSymbolAddress((void**)&p_bce, g_bce);
    cudaGetSymbolAddress((void**)&p_Wnode, g_Wnode);

    // fold weights (tiny)
    prep_kernel<<<255, 256>>>(W_emb2, b_emb2, Wf, bf, Ws, bs);

    // h0 = x @ W_emb1 + b_emb1    [50000,92]x[92,64]
    launch_gemm<FX, HD, 8, 32, 4>(x, W_emb1, b_emb1, p_h, NN);

    for (int a = 0; a < NCV; a++) {
        // EW = edge_attr @ Wce[a] + bce[a]   [800000,41]x[41,128]
        launch_gemm<FE, 2 * HD, 16, 16, 8>(edge_attr, p_Wce + a * FE * 2 * HD,
                                           p_bce + a * 2 * HD, p_EW, NE);
        // HN = h @ Wnode[a]                  [50000,64]x[64,256]
        launch_gemm<HD, 4 * HD, 32, 8, 8>(p_h, p_Wnode + (long long)a * HD * 4 * HD,
                                          nullptr, p_HN, NN);
        // acc = h (residual); zero BN stats; zero pool buffers before last layer
        copyzero_kernel<<<(NN * HD + 255) / 256, 256>>>(a == NCV - 1 ? 1 : 0);
        // messages + scatter-add
        edge_kernel<<<(NE * 16) / 256, 256>>>(ei);
        // BN stats
        stats_kernel<<<256, 256>>>();
        // normalize (+relu, +pool on last layer)
        bn_kernel<<<(NN * HD + 255) / 256, 256>>>(gamma + a * HD, beta + a * HD,
                                                  a < NCV - 1 ? 1 : 0,
                                                  a == NCV - 1 ? 1 : 0, batch);
    }

    // pooled mean -> softplus MLP -> output [128]
    mlp_kernel<<<1, 128>>>(W1, b1, W2, b2, Wo, bo, out);
}

// round 2
// speedup vs baseline: 1.3553x; 1.3553x over previous
#include <cuda_runtime.h>
#include <math.h>

#define NN 50000      // nodes
#define NE 800000     // edges
#define NG 128        // graphs
#define FX 92         // node feature dim
#define FE 41         // edge feature dim
#define HD 64         // hidden
#define NCV 3         // conv layers
#define BN_EPS 1e-5f

typedef unsigned long long ull;

// ---------------- device scratch ----------------
__device__ float g_h[NN * HD];                        // current node features
__device__ float g_acc[NN * HD];                      // residual + message accumulator
__device__ float g_HN[NN * 4 * HD];                   // [N,256]: h@[Wf_i|Wf_j|Ws_i|Ws_j]
__device__ float g_Wce[NCV * FE * 2 * HD];            // folded edge weights [3][41][128]
__device__ float g_bce[NCV * 2 * HD];                 // folded edge bias   [3][128]
__device__ float g_Wnode[NCV * HD * 4 * HD];          // node weights [3][64][256]
__device__ float g_sum[NCV * HD];
__device__ float g_sumsq[NCV * HD];
__device__ float g_gsum[NG * HD];
__device__ float g_gcnt[NG];

// ---------------- f32x2 packed math helpers ----------------
__device__ __forceinline__ ull pack2(float a, float b) {
    ull r; asm("mov.b64 %0, {%1, %2};" : "=l"(r) : "f"(a), "f"(b)); return r;
}
__device__ __forceinline__ void unpack2(ull v, float& a, float& b) {
    asm("mov.b64 {%0, %1}, %2;" : "=f"(a), "=f"(b) : "l"(v));
}
__device__ __forceinline__ void fma2(ull& d, ull a, ull b) {
    asm("fma.rn.f32x2 %0, %1, %2, %0;" : "+l"(d) : "l"(a), "l"(b));
}

__device__ __forceinline__ float sigmoid_f(float x) {
    return 1.0f / (1.0f + __expf(-x));
}
__device__ __forceinline__ float softplus_f(float x) {
    return fmaxf(x, 0.0f) + __logf(1.0f + __expf(-fabsf(x)));
}

// ---------------- prep: fold weights ----------------
__global__ void prep_kernel(const float* __restrict__ W_emb2, const float* __restrict__ b_emb2,
                            const float* __restrict__ Wf, const float* __restrict__ bf,
                            const float* __restrict__ Ws, const float* __restrict__ bs) {
    int idx = blockIdx.x * blockDim.x + threadIdx.x;
    const int N_WCE = NCV * FE * 2 * HD;  // 15744
    const int N_BCE = NCV * 2 * HD;       // 384
    const int N_WND = NCV * HD * 4 * HD;  // 49152
    if (idx < N_WCE) {
        int j = idx % (2 * HD);
        int k = (idx / (2 * HD)) % FE;
        int a = idx / (2 * HD * FE);
        const float* Wb = (j < HD) ? Wf : Ws;
        int jj = j & (HD - 1);
        float s = 0.f;
        #pragma unroll 8
        for (int m = 0; m < HD; m++)
            s = fmaf(W_emb2[k * HD + m], Wb[(a * 3 * HD + 2 * HD + m) * HD + jj], s);
        g_Wce[idx] = s;
    } else if (idx < N_WCE + N_BCE) {
        int t = idx - N_WCE;
        int j = t % (2 * HD);
        int a = t / (2 * HD);
        const float* Wb = (j < HD) ? Wf : Ws;
        const float* bb = (j < HD) ? bf : bs;
        int jj = j & (HD - 1);
        float s = bb[a * HD + jj];
        #pragma unroll 8
        for (int m = 0; m < HD; m++)
            s = fmaf(b_emb2[m], Wb[(a * 3 * HD + 2 * HD + m) * HD + jj], s);
        g_bce[t] = s;
    } else if (idx < N_WCE + N_BCE + N_WND) {
        int t = idx - N_WCE - N_BCE;
        int j = t % (4 * HD);
        int m = (t / (4 * HD)) % HD;
        int a = t / (4 * HD * HD);
        int blk = j / HD;
        int jj = j & (HD - 1);
        const float* Wsel = (blk < 2) ? Wf : Ws;
        int roff = (blk & 1) ? HD : 0;
        g_Wnode[t] = Wsel[(a * 3 * HD + roff + m) * HD + jj];
    }
}

// ---------------- generic fp32 GEMM with f32x2 inner loop ----------------
// C[:, c0:c0+NC] = A[M,K] @ B[K, c0:c0+NC] (+bias), B row stride = ldb, C row stride = ldc.
// c0 = blockIdx.y * NC.
template <int K, int NC, int CT, int RT, int RPT>
__global__ void gemm_bias_kernel(const float* __restrict__ A, const float* __restrict__ B,
                                 const float* __restrict__ bias, float* __restrict__ C,
                                 int M, int ldb, int ldc) {
    constexpr int TR = RT * RPT;
    constexpr int KP = K + 1;
    constexpr int NT = CT * RT;
    extern __shared__ float smem[];
    float* Bs = smem;             // K*NC
    float* As = smem + K * NC;    // TR*KP
    int tid = threadIdx.x;
    int tx = tid % CT;
    int ty = tid / CT;
    int c0 = blockIdx.y * NC;
    for (int i = tid; i < K * NC; i += NT) {
        int k = i / NC, c = i - k * NC;
        Bs[i] = B[k * ldb + c0 + c];
    }
    ull bp[4];
    #pragma unroll
    for (int c = 0; c < 4; c++) {
        float b0 = bias ? bias[c0 + tx * 8 + 2 * c] : 0.f;
        float b1 = bias ? bias[c0 + tx * 8 + 2 * c + 1] : 0.f;
        bp[c] = pack2(b0, b1);
    }

    for (int tile = blockIdx.x; (long long)tile * TR < M; tile += gridDim.x) {
        int row0 = tile * TR;
        __syncthreads();
        for (int i = tid; i < TR * K; i += NT) {
            int r = i / K;
            int k = i - r * K;
            int gr = row0 + r;
            As[r * KP + k] = (gr < M) ? A[(long long)gr * K + k] : 0.f;
        }
        __syncthreads();
        ull acc[RPT][4];
        #pragma unroll
        for (int r = 0; r < RPT; r++)
            #pragma unroll
            for (int c = 0; c < 4; c++) acc[r][c] = bp[c];
        for (int k = 0; k < K; k++) {
            float4 b0 = *reinterpret_cast<const float4*>(&Bs[k * NC + tx * 8]);
            float4 b1 = *reinterpret_cast<const float4*>(&Bs[k * NC + tx * 8 + 4]);
            ull p0 = pack2(b0.x, b0.y), p1 = pack2(b0.z, b0.w);
            ull p2 = pack2(b1.x, b1.y), p3 = pack2(b1.z, b1.w);
            #pragma unroll
            for (int r = 0; r < RPT; r++) {
                float a = As[(ty * RPT + r) * KP + k];
                ull ad = pack2(a, a);
                fma2(acc[r][0], ad, p0);
                fma2(acc[r][1], ad, p1);
                fma2(acc[r][2], ad, p2);
                fma2(acc[r][3], ad, p3);
            }
        }
        #pragma unroll
        for (int r = 0; r < RPT; r++) {
            int gr = row0 + ty * RPT + r;
            if (gr < M) {
                float o[8];
                #pragma unroll
                for (int c = 0; c < 4; c++) unpack2(acc[r][c], o[2 * c], o[2 * c + 1]);
                float* cp = &C[(long long)gr * ldc + c0 + tx * 8];
                *reinterpret_cast<float4*>(cp) = make_float4(o[0], o[1], o[2], o[3]);
                *reinterpret_cast<float4*>(cp + 4) = make_float4(o[4], o[5], o[6], o[7]);
            }
        }
    }
}

// ---------------- initial residual copy + zero all stat/pool buffers ----------------
__global__ void copyzero_kernel() {
    int idx4 = blockIdx.x * blockDim.x + threadIdx.x;   // over NN*16 float4s
    if (idx4 < NN * 16)
        reinterpret_cast<float4*>(g_acc)[idx4] = reinterpret_cast<const float4*>(g_h)[idx4];
    if (idx4 < NCV * HD) { g_sum[idx4] = 0.f; g_sumsq[idx4] = 0.f; }
    if (idx4 < NG * HD) g_gsum[idx4] = 0.f;
    if (idx4 < NG) g_gcnt[idx4] = 0.f;
}

// ---------------- fused: edge GEMM + message + scatter ----------------
// Per 128-edge tile: EW[128,128] = edge_attr[128,41] @ Wce + bce computed in registers,
// then gather HN, activations, red.v4 scatter into g_acc.
// Thread (tx in [0,16), ty in [0,16)): 8 edges (ty*8..) x (4 f-cols + 4 s-cols) at tx*4.
#define EPB 128
__global__ __launch_bounds__(256) void fused_edge_kernel(
        const float* __restrict__ edge_attr, const int* __restrict__ ei,
        const float* __restrict__ Wce, const float* __restrict__ bce) {
    __shared__ float Ws_s[FE * 2 * HD];       // [41][128] 21KB
    __shared__ float A_s[EPB][FE + 1];        // 21.5KB
    __shared__ int   src_s[EPB], dst_s[EPB];
    int tid = threadIdx.x;
    int tx = tid & 15, ty = tid >> 4;
    for (int i = tid; i < FE * 2 * HD; i += 256) Ws_s[i] = Wce[i];
    float4 bf4 = *reinterpret_cast<const float4*>(&bce[tx * 4]);
    float4 bs4 = *reinterpret_cast<const float4*>(&bce[HD + tx * 4]);
    ull bf0 = pack2(bf4.x, bf4.y), bf1 = pack2(bf4.z, bf4.w);
    ull bs0 = pack2(bs4.x, bs4.y), bs1 = pack2(bs4.z, bs4.w);

    const float4* HN4 = reinterpret_cast<const float4*>(g_HN);
    const int ntiles = NE / EPB;
    for (int tile = blockIdx.x; tile < ntiles; tile += gridDim.x) {
        int e0 = tile * EPB;
        __syncthreads();
        for (int i = tid; i < EPB * FE; i += 256) {
            int r = i / FE, k = i - r * FE;
            A_s[r][k] = edge_attr[(long long)(e0 + r) * FE + k];
        }
        if (tid < EPB) {
            src_s[tid] = ei[e0 + tid];
            dst_s[tid] = ei[NE + e0 + tid];
        }
        __syncthreads();

        ull af[8][2], as_[8][2];
        #pragma unroll
        for (int r = 0; r < 8; r++) {
            af[r][0] = bf0; af[r][1] = bf1;
            as_[r][0] = bs0; as_[r][1] = bs1;
        }
        for (int k = 0; k < FE; k++) {
            float4 wf = *reinterpret_cast<const float4*>(&Ws_s[k * 128 + tx * 4]);
            float4 ws = *reinterpret_cast<const float4*>(&Ws_s[k * 128 + HD + tx * 4]);
            ull wf0 = pack2(wf.x, wf.y), wf1 = pack2(wf.z, wf.w);
            ull ws0 = pack2(ws.x, ws.y), ws1 = pack2(ws.z, ws.w);
            #pragma unroll
            for (int r = 0; r < 8; r++) {
                float a = A_s[ty * 8 + r][k];
                ull ad = pack2(a, a);
                fma2(af[r][0], ad, wf0);
                fma2(af[r][1], ad, wf1);
                fma2(as_[r][0], ad, ws0);
                fma2(as_[r][1], ad, ws1);
            }
        }
        #pragma unroll
        for (int r = 0; r < 8; r++) {
            int er = ty * 8 + r;
            int s = src_s[er], d = dst_s[er];
            float4 fi = HN4[(long long)d * 64 + tx];
            float4 fj = HN4[(long long)s * 64 + 16 + tx];
            float4 si = HN4[(long long)d * 64 + 32 + tx];
            float4 sj = HN4[(long long)s * 64 + 48 + tx];
            float f0, f1, f2, f3, s0, s1, s2, s3;
            unpack2(af[r][0], f0, f1); unpack2(af[r][1], f2, f3);
            unpack2(as_[r][0], s0, s1); unpack2(as_[r][1], s2, s3);
            float m0 = sigmoid_f(f0 + fi.x + fj.x) * softplus_f(s0 + si.x + sj.x);
            float m1 = sigmoid_f(f1 + fi.y + fj.y) * softplus_f(s1 + si.y + sj.y);
            float m2 = sigmoid_f(f2 + fi.z + fj.z) * softplus_f(s2 + si.z + sj.z);
            float m3 = sigmoid_f(f3 + fi.w + fj.w) * softplus_f(s3 + si.w + sj.w);
            float* ap = &g_acc[(long long)d * HD + tx * 4];
            asm volatile("red.global.add.v4.f32 [%0], {%1,%2,%3,%4};"
                         :: "l"(ap), "f"(m0), "f"(m1), "f"(m2), "f"(m3) : "memory");
        }
    }
}

// ---------------- BN stats: per-column sum & sumsq (into layer slot a) ----------------
__global__ void stats_kernel(int a) {
    __shared__ float s_s[HD], s_q[HD];
    int tid = threadIdx.x;
    if (tid < HD) { s_s[tid] = 0.f; s_q[tid] = 0.f; }
    __syncthreads();
    int col4 = tid & 15;
    float4 ls = make_float4(0.f, 0.f, 0.f, 0.f), lq = ls;
    const float4* acc4 = reinterpret_cast<const float4*>(g_acc);
    for (int idx4 = blockIdx.x * blockDim.x + tid; idx4 < NN * 16; idx4 += gridDim.x * blockDim.x) {
        float4 v = acc4[idx4];
        ls.x += v.x; lq.x = fmaf(v.x, v.x, lq.x);
        ls.y += v.y; lq.y = fmaf(v.y, v.y, lq.y);
        ls.z += v.z; lq.z = fmaf(v.z, v.z, lq.z);
        ls.w += v.w; lq.w = fmaf(v.w, v.w, lq.w);
    }
    atomicAdd(&s_s[col4 * 4 + 0], ls.x); atomicAdd(&s_q[col4 * 4 + 0], lq.x);
    atomicAdd(&s_s[col4 * 4 + 1], ls.y); atomicAdd(&s_q[col4 * 4 + 1], lq.y);
    atomicAdd(&s_s[col4 * 4 + 2], ls.z); atomicAdd(&s_q[col4 * 4 + 2], lq.z);
    atomicAdd(&s_s[col4 * 4 + 3], ls.w); atomicAdd(&s_q[col4 * 4 + 3], lq.w);
    __syncthreads();
    if (tid < HD) {
        atomicAdd(&g_sum[a * HD + tid], s_s[tid]);
        atomicAdd(&g_sumsq[a * HD + tid], s_q[tid]);
    }
}

// ---------------- BN normalize (+relu) (+write next residual) (+fused pooling) ----------------
__global__ void bn_kernel(const float* __restrict__ gamma, const float* __restrict__ beta,
                          int a, int do_relu, int write_acc, int do_pool,
                          const int* __restrict__ batch) {
    int idx4 = blockIdx.x * blockDim.x + threadIdx.x;   // over NN*16 float4s
    if (idx4 >= NN * 16) return;
    int col4 = idx4 & 15;
    int node = idx4 >> 4;
    const float invn = 1.0f / (float)NN;
    float4 su = reinterpret_cast<const float4*>(g_sum)[a * 16 + col4];
    float4 sq = reinterpret_cast<const float4*>(g_sumsq)[a * 16 + col4];
    float4 ga = reinterpret_cast<const float4*>(gamma)[col4];
    float4 be = reinterpret_cast<const float4*>(beta)[col4];
    float4 v = reinterpret_cast<const float4*>(g_acc)[idx4];
    #pragma unroll
    for (int c = 0; c < 4; c++) {
        float mu = (&su.x)[c] * invn;
        float var = fmaxf((&sq.x)[c] * invn - mu * mu, 0.f);
        float y = ((&v.x)[c] - mu) * rsqrtf(var + BN_EPS) * (&ga.x)[c] + (&be.x)[c];
        if (do_relu) y = fmaxf(y, 0.f);
        (&v.x)[c] = y;
    }
    reinterpret_cast<float4*>(g_h)[idx4] = v;
    if (write_acc) reinterpret_cast<float4*>(g_acc)[idx4] = v;
    if (do_pool) {
        int b = batch[node];
        float* gp = &g_gsum[b * HD + col4 * 4];
        asm volatile("red.global.add.v4.f32 [%0], {%1,%2,%3,%4};"
                     :: "l"(gp), "f"(v.x), "f"(v.y), "f"(v.z), "f"(v.w) : "memory");
        if (col4 == 0) atomicAdd(&g_gcnt[b], 1.0f);
    }
}

// ---------------- final MLP: one block, one graph per thread ----------------
__global__ void mlp_kernel(const float* __restrict__ W1, const float* __restrict__ b1,
                           const float* __restrict__ W2, const float* __restrict__ b2,
                           const float* __restrict__ Wo, const float* __restrict__ bo,
                           float* __restrict__ out) {
    __shared__ float sW1[HD * HD], sW2[HD * HD], sWo[HD], sb1[HD], sb2[HD];
    int tid = threadIdx.x;
    for (int i = tid; i < HD * HD; i += blockDim.x) { sW1[i] = W1[i]; sW2[i] = W2[i]; }
    if (tid < HD) { sWo[tid] = Wo[tid]; sb1[tid] = b1[tid]; sb2[tid] = b2[tid]; }
    __syncthreads();
    if (tid < NG) {
        float inv = 1.0f / fmaxf(g_gcnt[tid], 1.0f);
        float v[HD], y[HD];
        #pragma unroll
        for (int k = 0; k < HD; k++) v[k] = g_gsum[tid * HD + k] * inv;
        #pragma unroll 1
        for (int j = 0; j < HD; j++) {
            float s = sb1[j];
            #pragma unroll
            for (int k = 0; k < HD; k++) s = fmaf(v[k], sW1[k * HD + j], s);
            y[j] = softplus_f(s);
        }
        float o = bo[0];
        #pragma unroll 1
        for (int j = 0; j < HD; j++) {
            float s = sb2[j];
            #pragma unroll
            for (int k = 0; k < HD; k++) s = fmaf(y[k], sW2[k * HD + j], s);
            o = fmaf(softplus_f(s), sWo[j], o);
        }
        out[tid] = o;
    }
}

// ---------------- host launcher ----------------
template <int K, int NC, int CT, int RT, int RPT>
static void launch_gemm(const float* A, const float* B, const float* bias, float* C,
                        int M, int ldb, int ldc, int nsplit) {
    constexpr int TR = RT * RPT;
    constexpr int KP = K + 1;
    static_assert(CT * 8 == NC, "col threads x 8 must equal NC");
    size_t sm = (size_t)(K * NC + TR * KP) * sizeof(float);
    if (sm > 48 * 1024) {
        cudaFuncSetAttribute(gemm_bias_kernel<K, NC, CT, RT, RPT>,
                             cudaFuncAttributeMaxDynamicSharedMemorySize, (int)sm);
    }
    dim3 grid((M + TR - 1) / TR, nsplit);
    gemm_bias_kernel<K, NC, CT, RT, RPT><<<grid, CT * RT, sm>>>(A, B, bias, C, M, ldb, ldc);
}

extern "C" void kernel_launch(void* const* d_in, const int* in_sizes, int n_in,
                              void* d_out, int out_size) {
    const float* x         = (const float*)d_in[0];
    const float* edge_attr = (const float*)d_in[1];
    const int*   ei        = (const int*)d_in[2];
    const int*   batch     = (const int*)d_in[3];
    const float* W_emb1    = (const float*)d_in[4];
    const float* b_emb1    = (const float*)d_in[5];
    const float* W_emb2    = (const float*)d_in[6];
    const float* b_emb2    = (const float*)d_in[7];
    const float* Wf        = (const float*)d_in[8];
    const float* bf        = (const float*)d_in[9];
    const float* Ws        = (const float*)d_in[10];
    const float* bs        = (const float*)d_in[11];
    const float* gamma     = (const float*)d_in[12];
    const float* beta      = (const float*)d_in[13];
    const float* W1        = (const float*)d_in[14];
    const float* b1        = (const float*)d_in[15];
    const float* W2        = (const float*)d_in[16];
    const float* b2        = (const float*)d_in[17];
    const float* Wo        = (const float*)d_in[18];
    const float* bo        = (const float*)d_in[19];
    float* out = (float*)d_out;

    float *p_h, *p_HN, *p_Wce, *p_bce, *p_Wnode;
    cudaGetSymbolAddress((void**)&p_h, g_h);
    cudaGetSymbolAddress((void**)&p_HN, g_HN);
    cudaGetSymbolAddress((void**)&p_Wce, g_Wce);
    cudaGetSymbolAddress((void**)&p_bce, g_bce);
    cudaGetSymbolAddress((void**)&p_Wnode, g_Wnode);

    // fold weights (tiny)
    prep_kernel<<<255, 256>>>(W_emb2, b_emb2, Wf, bf, Ws, bs);

    // h0 = x @ W_emb1 + b_emb1    [50000,92]x[92,64]
    launch_gemm<FX, HD, 8, 32, 4>(x, W_emb1, b_emb1, p_h, NN, HD, HD, 1);

    // acc = h0; zero all BN stat slots + pool buffers (once)
    copyzero_kernel<<<(NN * 16 + 255) / 256, 256>>>();

    for (int a = 0; a < NCV; a++) {
        // HN = h @ Wnode[a]   [50000,64]x[64,256], split over 2 column halves
        launch_gemm<HD, 2 * HD, 16, 16, 8>(p_h, p_Wnode + (long long)a * HD * 4 * HD,
                                           nullptr, p_HN, NN, 4 * HD, 4 * HD, 2);
        // fused edge GEMM + message + scatter into g_acc
        fused_edge_kernel<<<888, 256>>>(edge_attr, ei,
                                        p_Wce + a * FE * 2 * HD, p_bce + a * 2 * HD);
        // BN stats into slot a
        stats_kernel<<<296, 256>>>(a);
        // normalize (+relu for a<2; write next residual for a<2; pool on last)
        bn_kernel<<<(NN * 16 + 255) / 256, 256>>>(gamma + a * HD, beta + a * HD, a,
                                                  a < NCV - 1 ? 1 : 0,
                                                  a < NCV - 1 ? 1 : 0,
                                                  a == NCV - 1 ? 1 : 0, batch);
    }

    // pooled mean -> softplus MLP -> output [128]
    mlp_kernel<<<1, 128>>>(W1, b1, W2, b2, Wo, bo, out);
}